// round 11
// baseline (speedup 1.0000x reference)
#include <cuda_runtime.h>
#include <cuda_bf16.h>

#define NNODES 100000
#define NEDGES 600000
#define DFEAT  128

// Scratch. g_deg starts zero (static zero-init) and is re-zeroed by k_norm
// each run -> every execution sees identical initial state (deterministic).
__device__ float g_deg[NNODES];    // degree count (without self loop)
__device__ float g_dis[NNODES];    // rsqrt(1 + deg)
__device__ float g_s[NNODES];      // raw dot products x·w
__device__ float g_p[NNODES];      // p0 = dis * s
__device__ float g_acc[NNODES];    // round-1 accumulator (init = p0)
__device__ float g_p2[NNODES];     // p1 = dis^2 * acc1
__device__ float g_acc2[NNODES];   // round-2 accumulator (init = p1)

// Fused kernel: interleaved block roles so HBM-bound dot blocks and
// L2-atomic-bound count blocks are co-resident from the first wave.
// Group of 11 blocks = 8 dot + 3 count.
#define DOT_BLOCKS 3125   // 8 warps/block * 4 nodes/warp * 3125 = 100000 exactly
#define CNT_BLOCKS 1172   // 256 thr * 2 edges * 1172 = 600064 >= 600000
#define NGROUPS    391
#define TOT_BLOCKS (NGROUPS * 11)   // 4301

__global__ void k_fused(const float* __restrict__ x,
                        const float* __restrict__ w,
                        const int* __restrict__ ei) {
    int g = blockIdx.x / 11;
    int r = blockIdx.x % 11;

    if (r >= 8) {
        // ---- count role: 2 edges/thread ----
        int cbid = g * 3 + (r - 8);
        if (cbid >= CNT_BLOCKS) return;
        int e = (cbid * 256 + (int)threadIdx.x) * 2;
        if (e < NEDGES) {
            int2 c2 = *reinterpret_cast<const int2*>(ei + NEDGES + e);
            atomicAdd(&g_deg[c2.x], 1.0f);
            atomicAdd(&g_deg[c2.y], 1.0f);
        }
        return;
    }

    // ---- dot role: 4 nodes/warp, MLP=4 ----
    int dbid = g * 8 + r;
    if (dbid >= DOT_BLOCKS) return;
    int warp_id = dbid * 8 + ((int)threadIdx.x >> 5);
    int lane = threadIdx.x & 31;
    int base = warp_id * 4;            // 3125*8*4 == NNODES, no guard needed

    const float4* wr = reinterpret_cast<const float4*>(w);
    float4 wv = __ldg(&wr[lane]);

    float4 xv0 = reinterpret_cast<const float4*>(x + (size_t)(base + 0) * DFEAT)[lane];
    float4 xv1 = reinterpret_cast<const float4*>(x + (size_t)(base + 1) * DFEAT)[lane];
    float4 xv2 = reinterpret_cast<const float4*>(x + (size_t)(base + 2) * DFEAT)[lane];
    float4 xv3 = reinterpret_cast<const float4*>(x + (size_t)(base + 3) * DFEAT)[lane];

    float s0 = xv0.x * wv.x + xv0.y * wv.y + xv0.z * wv.z + xv0.w * wv.w;
    float s1 = xv1.x * wv.x + xv1.y * wv.y + xv1.z * wv.z + xv1.w * wv.w;
    float s2 = xv2.x * wv.x + xv2.y * wv.y + xv2.z * wv.z + xv2.w * wv.w;
    float s3 = xv3.x * wv.x + xv3.y * wv.y + xv3.z * wv.z + xv3.w * wv.w;

    #pragma unroll
    for (int off = 16; off > 0; off >>= 1) {
        s0 += __shfl_xor_sync(0xFFFFFFFFu, s0, off);
        s1 += __shfl_xor_sync(0xFFFFFFFFu, s1, off);
        s2 += __shfl_xor_sync(0xFFFFFFFFu, s2, off);
        s3 += __shfl_xor_sync(0xFFFFFFFFu, s3, off);
    }

    if (lane == 0) {
        *reinterpret_cast<float4*>(&g_s[base]) = make_float4(s0, s1, s2, s3);
    }
}

// k_norm: dis = rsqrt(1+deg); p0 = dis*s; acc1 init = p0; reset deg for next run
__global__ void k_norm() {
    int i = blockIdx.x * blockDim.x + threadIdx.x;
    if (i < NNODES) {
        float d = rsqrtf(1.0f + g_deg[i]);
        g_deg[i] = 0.0f;              // self-clearing for next execution
        g_dis[i] = d;
        float p = d * g_s[i];
        g_p[i]   = p;
        g_acc[i] = p;
    }
}

// round-1 edges: acc1[col] += p0[row]; 1 edge/thread (wavefront floor config)
__global__ void k_edge1(const int* __restrict__ ei) {
    int e = blockIdx.x * blockDim.x + threadIdx.x;
    if (e < NEDGES) {
        int row = __ldg(&ei[e]);
        int col = __ldg(&ei[NEDGES + e]);
        atomicAdd(&g_acc[col], __ldg(&g_p[row]));
    }
}

// p1 = dis^2 * acc1 ; acc2 init = p1
__global__ void k_pre2() {
    int i = blockIdx.x * blockDim.x + threadIdx.x;
    if (i < NNODES) {
        float dd = g_dis[i];
        float v = dd * dd * g_acc[i];
        g_p2[i]   = v;
        g_acc2[i] = v;
    }
}

// round-2 edges: acc2[col] += p1[row]
__global__ void k_edge2(const int* __restrict__ ei) {
    int e = blockIdx.x * blockDim.x + threadIdx.x;
    if (e < NEDGES) {
        int row = __ldg(&ei[e]);
        int col = __ldg(&ei[NEDGES + e]);
        atomicAdd(&g_acc2[col], __ldg(&g_p2[row]));
    }
}

// out = dis * acc2 + b
__global__ void k_post(float* __restrict__ out, const float* __restrict__ b) {
    int i = blockIdx.x * blockDim.x + threadIdx.x;
    if (i < NNODES) {
        out[i] = g_dis[i] * g_acc2[i] + b[0];
    }
}

extern "C" void kernel_launch(void* const* d_in, const int* in_sizes, int n_in,
                              void* d_out, int out_size) {
    const float* x  = (const float*)d_in[0];
    const int*   ei = (const int*)d_in[1];
    const float* W  = (const float*)d_in[2];
    const float* b  = (const float*)d_in[3];
    float* out = (float*)d_out;

    const int T = 256;
    const int gN = (NNODES + T - 1) / T;
    const int gE = (NEDGES + T - 1) / T;   // 1 edge/thread

    k_fused<<<TOT_BLOCKS, T>>>(x, W, ei);  // overlapped count + dot
    k_norm<<<gN, T>>>();
    k_edge1<<<gE, T>>>(ei);
    k_pre2<<<gN, T>>>();
    k_edge2<<<gE, T>>>(ei);
    k_post<<<gN, T>>>(out, b);
}